// round 1
// baseline (speedup 1.0000x reference)
#include <cuda_runtime.h>
#include <cuda_bf16.h>
#include <cstdint>

// ---------------------------------------------------------------------------
// SupConLossWithQueue
//   Q=4096, bsz=256, B=4352, 2B=8704, D=128, TEMP=0.07
//   rows kept: g in [3841, 8193)  (4352 rows)
// ---------------------------------------------------------------------------
#define Qn      4096
#define BSZh    256
#define Bn      4352            // Q + bsz
#define N2      8704            // 2*B
#define Dk      128
#define ROW0    3841
#define NR      4352            // number of selected rows
#define INV_T   14.2857142857142857f   // 1/0.07

// ---------------- device scratch (no runtime allocation allowed) -----------
__device__ __nv_bfloat16 g_cB[N2][Dk];   // contrast, bf16 (MMA operand)
__device__ float         g_cF[N2][Dk];   // contrast, fp32 (exact positive dots)
__device__ int           g_lab[N2];      // tiled labels
__device__ float         g_rowLSE[NR];   // per selected row: log sum_{lab!=} exp(d/T)
__device__ float         g_rowVal[NR];   // per selected row: mean_log_prob_pos

// ---------------------------------------------------------------------------
// Kernel P: gather contrast rows + labels
// grid = N2 blocks of 128 threads; block c builds column/row c
// ---------------------------------------------------------------------------
__global__ void kprep(const float* __restrict__ feat,   // (512,128) flat
                      const int*   __restrict__ label,  // (256)
                      const float* __restrict__ fq,     // (4096,128)
                      const float* __restrict__ fq2,    // (4096,128)
                      const int*   __restrict__ lq)     // (4096)
{
    int c = blockIdx.x;
    int k = threadIdx.x;
    int half = (c >= Bn) ? 1 : 0;
    int i = c - half * Bn;

    const float* src;
    if (i < BSZh)      src = feat + (half ? i : (BSZh + i)) * Dk;        // f1 / f2
    else if (i < Qn)   src = (half ? fq2 : fq) + i * Dk;                 // queues
    else               src = feat + ((half ? BSZh : 0) + (i - Qn)) * Dk; // f1/f2 tail

    float v = src[k];
    g_cF[c][k] = v;
    g_cB[c][k] = __float2bfloat16(v);
    if (k == 0) {
        int L = (i < BSZh) ? label[i] : ((i < Qn) ? lq[i] : label[i - Qn]);
        g_lab[c] = L;
    }
}

// ---------------------------------------------------------------------------
// Kernel G: bf16 mma GEMM (rows 3841..8192 x all 8704 cols, K=128) fused with
// masked online logsumexp (mask = labels differ).
// 136 blocks x 256 threads; block tile M=32, N-loop in 128-col tiles.
// ---------------------------------------------------------------------------
#define SM_A     0               // 32 rows * 272B   = 8704 B (bf16, stride 136 halves)
#define SM_U     8704            // union: B tile (128*272B=34816) / S tile (32*132*4=16896)
#define SM_LAB   (8704+34816)    // 128 ints
#define SM_M     (8704+34816+512)
#define SM_Z     (SM_M+128)
#define SM_RL    (SM_Z+128)
#define SM_TOTAL (SM_RL+128)     // 44.5 KB < 48 KB static limit

__device__ __forceinline__ void mma16816(float* c, const uint32_t* a, uint32_t b0, uint32_t b1)
{
    asm volatile(
        "mma.sync.aligned.m16n8k16.row.col.f32.bf16.bf16.f32 "
        "{%0,%1,%2,%3}, {%4,%5,%6,%7}, {%8,%9}, {%0,%1,%2,%3};\n"
        : "+f"(c[0]), "+f"(c[1]), "+f"(c[2]), "+f"(c[3])
        : "r"(a[0]), "r"(a[1]), "r"(a[2]), "r"(a[3]), "r"(b0), "r"(b1));
}

__global__ void __launch_bounds__(256) kgemm()
{
    __shared__ __align__(16) unsigned char sm[SM_TOTAL];
    __nv_bfloat16* sA = (__nv_bfloat16*)(sm + SM_A);
    __nv_bfloat16* sB = (__nv_bfloat16*)(sm + SM_U);
    float*         sS = (float*)(sm + SM_U);          // union with sB
    int*         sLab = (int*)(sm + SM_LAB);
    float*         sM = (float*)(sm + SM_M);
    float*         sZ = (float*)(sm + SM_Z);
    int*          sRL = (int*)(sm + SM_RL);

    const int tid  = threadIdx.x;
    const int lane = tid & 31;
    const int wid  = tid >> 5;
    const int wm   = wid >> 2;     // 0..1  (M 16-row half)
    const int wn   = wid & 3;      // 0..3  (N 32-col strip)
    const int rowbase = blockIdx.x * 32;

    // --- load A tile (32 rows x 128 bf16), padded stride 272B ---
    for (int idx = tid; idx < 32 * 16; idx += 256) {
        int r = idx >> 4, ch = idx & 15;
        *(uint4*)((char*)sA + r * 272 + ch * 16) =
            *(const uint4*)((const char*)g_cB[ROW0 + rowbase + r] + ch * 16);
    }
    if (tid < 32) {
        sM[tid] = -1e30f;
        sZ[tid] = 0.f;
        sRL[tid] = g_lab[ROW0 + rowbase + tid];
    }
    __syncthreads();

    // --- preload all A fragments (8 k-steps x 4 regs) ---
    uint32_t afr[8][4];
    {
        uint32_t abase = (uint32_t)__cvta_generic_to_shared(sA);
        uint32_t addr0 = abase + (wm * 16 + (lane & 15)) * 272 + ((lane >> 4) << 4);
#pragma unroll
        for (int ks = 0; ks < 8; ks++) {
            uint32_t a = addr0 + ks * 32;
            asm volatile("ldmatrix.sync.aligned.m8n8.x4.shared.b16 {%0,%1,%2,%3}, [%4];"
                         : "=r"(afr[ks][0]), "=r"(afr[ks][1]), "=r"(afr[ks][2]), "=r"(afr[ks][3])
                         : "r"(a));
        }
    }

    uint32_t bbase = (uint32_t)__cvta_generic_to_shared(sB);
    const int bj = lane >> 3;                              // 0..3 (ldmatrix sub-matrix)
    const int bn_off = ((bj & 2) << 2) + (lane & 7);       // n within 16-col group
    const uint32_t bk_off = (uint32_t)((bj & 1) << 4);     // k half (bytes)

    for (int nb = 0; nb < N2 / 128; nb++) {
        const int n0g = nb * 128;
        __syncthreads();   // prior epilogue done with sS (union w/ sB)

        // --- load B tile (128 cols x 128 bf16) ---
        for (int idx = tid; idx < 128 * 16; idx += 256) {
            int r = idx >> 4, ch = idx & 15;
            *(uint4*)((char*)sB + r * 272 + ch * 16) =
                *(const uint4*)((const char*)g_cB[n0g + r] + ch * 16);
        }
        if (tid < 128) sLab[tid] = g_lab[n0g + tid];
        __syncthreads();

        // --- MMA: 16(M) x 32(N) per warp, K=128 ---
        float acc[4][4] = {};
#pragma unroll
        for (int ks = 0; ks < 8; ks++) {
#pragma unroll
            for (int gix = 0; gix < 2; gix++) {
                uint32_t ba = bbase + (uint32_t)((wn * 32 + gix * 16 + bn_off) * 272)
                              + (uint32_t)(ks * 32) + bk_off;
                uint32_t b0, b1, b2, b3;
                asm volatile("ldmatrix.sync.aligned.m8n8.x4.shared.b16 {%0,%1,%2,%3}, [%4];"
                             : "=r"(b0), "=r"(b1), "=r"(b2), "=r"(b3) : "r"(ba));
                mma16816(acc[2 * gix],     afr[ks], b0, b1);
                mma16816(acc[2 * gix + 1], afr[ks], b2, b3);
            }
        }
        __syncthreads();   // all warps done reading sB before overwriting as sS

        // --- stage accumulators into smem S (stride 132 floats) ---
        {
            int r0 = wm * 16 + (lane >> 2);
            int c0 = wn * 32 + ((lane & 3) << 1);
#pragma unroll
            for (int f = 0; f < 4; f++) {
                sS[r0 * 132 + c0 + f * 8]           = acc[f][0];
                sS[r0 * 132 + c0 + f * 8 + 1]       = acc[f][1];
                sS[(r0 + 8) * 132 + c0 + f * 8]     = acc[f][2];
                sS[(r0 + 8) * 132 + c0 + f * 8 + 1] = acc[f][3];
            }
        }
        __syncthreads();

        // --- fused masked online logsumexp epilogue ---
        {
            int r = tid >> 3, sub = tid & 7;    // 8 threads per row, cols sub, sub+8, ...
            int rl = sRL[r];
            float oldm = sM[r], oldz = sZ[r];
            float vals[16];
            int mbits = 0;
            float lm = -1e30f;
#pragma unroll
            for (int q = 0; q < 16; q++) {
                int col = q * 8 + sub;
                float v = sS[r * 132 + col] * INV_T;
                vals[q] = v;
                if (sLab[col] != rl) { mbits |= (1 << q); lm = fmaxf(lm, v); }
            }
            lm = fmaxf(lm, __shfl_xor_sync(0xffffffffu, lm, 1));
            lm = fmaxf(lm, __shfl_xor_sync(0xffffffffu, lm, 2));
            lm = fmaxf(lm, __shfl_xor_sync(0xffffffffu, lm, 4));
            float newm = fmaxf(oldm, lm);
            float zs = 0.f;
#pragma unroll
            for (int q = 0; q < 16; q++)
                if ((mbits >> q) & 1) zs += __expf(vals[q] - newm);
            zs += __shfl_xor_sync(0xffffffffu, zs, 1);
            zs += __shfl_xor_sync(0xffffffffu, zs, 2);
            zs += __shfl_xor_sync(0xffffffffu, zs, 4);
            if (sub == 0) {
                sZ[r] = oldz * __expf(oldm - newm) + zs;
                sM[r] = newm;
            }
        }
    }
    __syncthreads();
    if (tid < 32)
        g_rowLSE[rowbase + tid] = sM[tid] + __logf(sZ[tid]);
}

// ---------------------------------------------------------------------------
// Kernel R: one warp per selected row. Re-dot only same-label (positive)
// columns in exact fp32; apply min(0, d/T - LSE); mean over positives.
// ---------------------------------------------------------------------------
__global__ void __launch_bounds__(256) krow()
{
    int w = (blockIdx.x * blockDim.x + threadIdx.x) >> 5;
    if (w >= NR) return;
    int lane = threadIdx.x & 31;

    int g  = ROW0 + w;
    int rl = g_lab[g];
    float lse = g_rowLSE[w];
    bool exc = (g < Bn) || (g == 8192);   // self excluded from positives

    float4 rv = *(const float4*)(g_cF[g] + lane * 4);

    float sum = 0.f;
    int cnt = 0;
    for (int base = 0; base < N2; base += 32) {
        int lc = g_lab[base + lane];
        unsigned bal = __ballot_sync(0xffffffffu, lc == rl);
        while (bal) {
            int c = base + (__ffs(bal) - 1);
            bal &= bal - 1;
            if (exc && c == g) continue;
            float4 cv = *(const float4*)(g_cF[c] + lane * 4);
            float p = rv.x * cv.x + rv.y * cv.y + rv.z * cv.z + rv.w * cv.w;
            p += __shfl_xor_sync(0xffffffffu, p, 16);
            p += __shfl_xor_sync(0xffffffffu, p, 8);
            p += __shfl_xor_sync(0xffffffffu, p, 4);
            p += __shfl_xor_sync(0xffffffffu, p, 2);
            p += __shfl_xor_sync(0xffffffffu, p, 1);
            float x = p * INV_T - lse;
            sum += fminf(0.f, x);
            cnt++;
        }
    }
    if (lane == 0) g_rowVal[w] = sum / (float)cnt;
}

// ---------------------------------------------------------------------------
// Kernel F: loss = -mean(rowVal); write 3 identical outputs
// ---------------------------------------------------------------------------
__global__ void kfinal(float* __restrict__ out)
{
    __shared__ float sr[256];
    int tid = threadIdx.x;
    float a = 0.f;
    for (int i = tid; i < NR; i += 256) a += g_rowVal[i];
    sr[tid] = a;
    __syncthreads();
    for (int s = 128; s > 0; s >>= 1) {
        if (tid < s) sr[tid] += sr[tid + s];
        __syncthreads();
    }
    if (tid == 0) {
        float loss = -(sr[0] / (float)NR);
        out[0] = loss; out[1] = loss; out[2] = loss;
    }
}

// ---------------------------------------------------------------------------
extern "C" void kernel_launch(void* const* d_in, const int* in_sizes, int n_in,
                              void* d_out, int out_size)
{
    const float* feat  = (const float*)d_in[0];   // features (256,2,128)
    const int*   label = (const int*)d_in[1];     // (256)
    const float* fq    = (const float*)d_in[2];   // (4096,128)
    const float* fq2   = (const float*)d_in[3];   // (4096,128)
    const int*   lq    = (const int*)d_in[4];     // (4096)
    float* out = (float*)d_out;

    kprep<<<N2, Dk>>>(feat, label, fq, fq2, lq);
    kgemm<<<NR / 32, 256>>>();
    krow<<<NR / 8, 256>>>();
    kfinal<<<1, 256>>>(out);
}

// round 2
// speedup vs baseline: 1.6161x; 1.6161x over previous
#include <cuda_runtime.h>
#include <cuda_bf16.h>
#include <cstdint>

// ---------------------------------------------------------------------------
// SupConLossWithQueue:  Q=4096, bsz=256, B=4352, 2B=8704, D=128, T=0.07
// selected rows g in [3841, 8193)
// Key identities:
//   log_prob(g,c) = d(g,c)/T - log( sum_{c': lab(c')!=lab(g)} exp(d(g,c')/T) )
//   (global row-max cancels; d/T <= 14.3 so no max tracking needed in fp32)
//   positives of row g = columns with lab==lab(g), minus self iff
//   g in [3841,4352) or g==8192.
// ---------------------------------------------------------------------------
#define Qn      4096
#define BSZh    256
#define Bn      4352
#define N2      8704
#define Dk      128
#define ROW0    3841
#define NR      4352
#define NCLS    100
#define INV_T   14.2857142857142857f

__device__ __nv_bfloat16 g_cB[N2][Dk];
__device__ float         g_cF[N2][Dk];
__device__ int           g_lab[N2];
__device__ float         g_rowLSE[NR];
__device__ float         g_rowVal[NR];
__device__ int           g_clsOff[NCLS + 1];
__device__ int           g_clsList[N2];
__device__ unsigned int  g_ctr;

// ---------------------------------------------------------------------------
// Kernel P: gather contrast rows + labels (vectorized, float4 per thread)
// ---------------------------------------------------------------------------
__global__ void __launch_bounds__(256) kprep(const float* __restrict__ feat,
                                             const int*   __restrict__ label,
                                             const float* __restrict__ fq,
                                             const float* __restrict__ fq2,
                                             const int*   __restrict__ lq)
{
    int gid = blockIdx.x * 256 + threadIdx.x;   // 0 .. N2*32-1
    int c = gid >> 5, q = gid & 31;
    int half = (c >= Bn) ? 1 : 0;
    int i = c - half * Bn;

    const float* src;
    if (i < BSZh)      src = feat + (half ? i : (BSZh + i)) * Dk;
    else if (i < Qn)   src = (half ? fq2 : fq) + i * Dk;
    else               src = feat + ((half ? BSZh : 0) + (i - Qn)) * Dk;

    float4 v = *(const float4*)(src + q * 4);
    *(float4*)(&g_cF[c][q * 4]) = v;
    __nv_bfloat162 b01, b23;
    b01.x = __float2bfloat16(v.x); b01.y = __float2bfloat16(v.y);
    b23.x = __float2bfloat16(v.z); b23.y = __float2bfloat16(v.w);
    *(__nv_bfloat162*)(&g_cB[c][q * 4])     = b01;
    *(__nv_bfloat162*)(&g_cB[c][q * 4 + 2]) = b23;
    if (q == 0) {
        int L = (i < BSZh) ? label[i] : ((i < Qn) ? lq[i] : label[i - Qn]);
        g_lab[c] = L;
    }
}

// ---------------------------------------------------------------------------
// Kernel B: class buckets (histogram + prefix + scatter); also resets g_ctr
// ---------------------------------------------------------------------------
__global__ void kbucket()
{
    __shared__ int scnt[NCLS], soff[NCLS + 1];
    int tid = threadIdx.x;   // 1024
    if (tid < NCLS) scnt[tid] = 0;
    __syncthreads();
    for (int c = tid; c < N2; c += 1024) atomicAdd(&scnt[g_lab[c]], 1);
    __syncthreads();
    if (tid == 0) {
        int run = 0;
        for (int k = 0; k < NCLS; k++) { soff[k] = run; run += scnt[k]; }
        soff[NCLS] = run;
        g_ctr = 0u;
    }
    __syncthreads();
    if (tid <= NCLS) g_clsOff[tid] = soff[tid];
    if (tid < NCLS)  scnt[tid] = soff[tid];
    __syncthreads();
    for (int c = tid; c < N2; c += 1024) {
        int p = atomicAdd(&scnt[g_lab[c]], 1);
        g_clsList[p] = c;
    }
}

// ---------------------------------------------------------------------------
// Kernel G: bf16 mma GEMM fused with masked sum-of-exp (denominator).
// 136 blocks x 256 threads, M-tile 32, N streamed in 128-col tiles.
// Register-prefetched B pipeline; register-resident epilogue; 2 syncs/tile.
// ---------------------------------------------------------------------------
#define SMA   0                      // 32*272  = 8704
#define SMB   8704                   // 128*272 = 34816
#define SMLAB (8704 + 34816)         // 512
#define SMZ   (SMLAB + 512)          // 4*32*4  = 512
#define SMT   (SMZ + 512)            // 45056 B

__device__ __forceinline__ void mma16816(float* c, const uint32_t* a, uint32_t b0, uint32_t b1)
{
    asm volatile(
        "mma.sync.aligned.m16n8k16.row.col.f32.bf16.bf16.f32 "
        "{%0,%1,%2,%3}, {%4,%5,%6,%7}, {%8,%9}, {%0,%1,%2,%3};\n"
        : "+f"(c[0]), "+f"(c[1]), "+f"(c[2]), "+f"(c[3])
        : "r"(a[0]), "r"(a[1]), "r"(a[2]), "r"(a[3]), "r"(b0), "r"(b1));
}

__global__ void __launch_bounds__(256) kgemm()
{
    __shared__ __align__(16) unsigned char sm[SMT];
    __nv_bfloat16* sA = (__nv_bfloat16*)(sm + SMA);
    __nv_bfloat16* sB = (__nv_bfloat16*)(sm + SMB);
    int*         sLab = (int*)(sm + SMLAB);
    float*         sZ = (float*)(sm + SMZ);

    const int tid  = threadIdx.x;
    const int lane = tid & 31;
    const int wid  = tid >> 5;
    const int wm   = wid >> 2;     // 0..1
    const int wn   = wid & 3;      // 0..3
    const int rowbase = blockIdx.x * 32;

    // A tile: 32 rows x 128 bf16, padded stride 272B
    for (int idx = tid; idx < 32 * 16; idx += 256) {
        int r = idx >> 4, ch = idx & 15;
        *(uint4*)((char*)sA + r * 272 + ch * 16) =
            *(const uint4*)((const char*)g_cB[ROW0 + rowbase + r] + ch * 16);
    }
    __syncthreads();

    // preload A fragments (8 k-steps x 4 regs)
    uint32_t afr[8][4];
    {
        uint32_t abase = (uint32_t)__cvta_generic_to_shared(sA);
        uint32_t addr0 = abase + (wm * 16 + (lane & 15)) * 272 + ((lane >> 4) << 4);
#pragma unroll
        for (int ks = 0; ks < 8; ks++) {
            uint32_t a = addr0 + ks * 32;
            asm volatile("ldmatrix.sync.aligned.m8n8.x4.shared.b16 {%0,%1,%2,%3}, [%4];"
                         : "=r"(afr[ks][0]), "=r"(afr[ks][1]), "=r"(afr[ks][2]), "=r"(afr[ks][3])
                         : "r"(a));
        }
    }

    // row labels for this thread's two accumulator rows
    const int rbl = rowbase + wm * 16 + (lane >> 2);
    const int rl0 = g_lab[ROW0 + rbl];
    const int rl1 = g_lab[ROW0 + rbl + 8];

    float z0 = 0.f, z1 = 0.f;

    // B prefetch: 8 x uint4 per thread
    const int br0 = tid >> 4;        // rows br0, br0+16, ... (+16 per j)
    const int bch = tid & 15;
    uint4 breg[8];
#pragma unroll
    for (int j = 0; j < 8; j++)
        breg[j] = *(const uint4*)((const char*)g_cB[br0 + j * 16] + bch * 16);
    int labreg = (tid < 128) ? g_lab[tid] : 0;

    uint32_t bbase = (uint32_t)__cvta_generic_to_shared(sB);
    const int bj = lane >> 3;
    const int bn_off = ((bj & 2) << 2) + (lane & 7);
    const uint32_t bk_off = (uint32_t)((bj & 1) << 4);

    for (int nb = 0; nb < N2 / 128; nb++) {
        // commit prefetched tile to smem
#pragma unroll
        for (int j = 0; j < 8; j++)
            *(uint4*)((char*)sB + (br0 + j * 16) * 272 + bch * 16) = breg[j];
        if (tid < 128) sLab[tid] = labreg;
        __syncthreads();

        // prefetch next tile (overlaps MMA + epilogue below)
        if (nb + 1 < N2 / 128) {
            int n0n = (nb + 1) * 128;
#pragma unroll
            for (int j = 0; j < 8; j++)
                breg[j] = *(const uint4*)((const char*)g_cB[n0n + br0 + j * 16] + bch * 16);
            if (tid < 128) labreg = g_lab[n0n + tid];
        }

        // MMA: 16(M) x 32(N) per warp, K=128
        float acc[4][4] = {};
#pragma unroll
        for (int ks = 0; ks < 8; ks++) {
#pragma unroll
            for (int gix = 0; gix < 2; gix++) {
                uint32_t ba = bbase + (uint32_t)((wn * 32 + gix * 16 + bn_off) * 272)
                              + (uint32_t)(ks * 32) + bk_off;
                uint32_t b0, b1, b2, b3;
                asm volatile("ldmatrix.sync.aligned.m8n8.x4.shared.b16 {%0,%1,%2,%3}, [%4];"
                             : "=r"(b0), "=r"(b1), "=r"(b2), "=r"(b3) : "r"(ba));
                mma16816(acc[2 * gix],     afr[ks], b0, b1);
                mma16816(acc[2 * gix + 1], afr[ks], b2, b3);
            }
        }

        // register epilogue: masked sum of exp(d/T)  (d/T <= 14.3, no max needed)
        float zl0 = 0.f, zl1 = 0.f;
#pragma unroll
        for (int f = 0; f < 4; f++) {
            int2 lp = *(const int2*)&sLab[wn * 32 + f * 8 + 2 * (lane & 3)];
            zl0 += __expf(lp.x != rl0 ? acc[f][0] * INV_T : -2e30f);
            zl0 += __expf(lp.y != rl0 ? acc[f][1] * INV_T : -2e30f);
            zl1 += __expf(lp.x != rl1 ? acc[f][2] * INV_T : -2e30f);
            zl1 += __expf(lp.y != rl1 ? acc[f][3] * INV_T : -2e30f);
        }
        z0 += zl0; z1 += zl1;
        __syncthreads();   // epilogue done reading sLab; safe to overwrite sB/sLab
    }

    // reduce z across the 4 threads sharing each row
    z0 += __shfl_xor_sync(0xffffffffu, z0, 1);
    z0 += __shfl_xor_sync(0xffffffffu, z0, 2);
    z1 += __shfl_xor_sync(0xffffffffu, z1, 1);
    z1 += __shfl_xor_sync(0xffffffffu, z1, 2);
    if ((lane & 3) == 0) {
        int r = wm * 16 + (lane >> 2);
        sZ[wn * 32 + r]     = z0;
        sZ[wn * 32 + r + 8] = z1;
    }
    __syncthreads();
    if (tid < 32) {
        float z = (sZ[tid] + sZ[32 + tid]) + (sZ[64 + tid] + sZ[96 + tid]);
        g_rowLSE[rowbase + tid] = __logf(z);
    }
}

// ---------------------------------------------------------------------------
// Kernel R: warp per row; lanes own whole positives via class bucket list.
// Fused final mean via last-block pattern.
// ---------------------------------------------------------------------------
__global__ void __launch_bounds__(256) krow(float* __restrict__ out)
{
    __shared__ float srow[8][128];
    __shared__ float sr[256];
    __shared__ bool amLast;

    int tid = threadIdx.x, lane = tid & 31, wid = tid >> 5;
    int w = blockIdx.x * 8 + wid;
    int g = ROW0 + w;
    int rl = g_lab[g];
    float lse = g_rowLSE[w];
    bool exc = (g < Bn) || (g == 8192);

    *(float4*)&srow[wid][lane * 4] = *(const float4*)&g_cF[g][lane * 4];
    __syncwarp();

    int off = g_clsOff[rl], end = g_clsOff[rl + 1];
    const float* rp = srow[wid];
    float s = 0.f;
    for (int idx = off + lane; idx < end; idx += 32) {
        int c = g_clsList[idx];
        if (exc && c == g) continue;
        const float* cp = g_cF[c];
        float a0 = 0.f, a1 = 0.f, a2 = 0.f, a3 = 0.f;
#pragma unroll
        for (int j = 0; j < 32; j += 4) {
            float4 r0 = *(const float4*)(rp + j * 4);
            float4 c0 = *(const float4*)(cp + j * 4);
            a0 += r0.x * c0.x + r0.y * c0.y + r0.z * c0.z + r0.w * c0.w;
            float4 r1 = *(const float4*)(rp + (j + 1) * 4);
            float4 c1 = *(const float4*)(cp + (j + 1) * 4);
            a1 += r1.x * c1.x + r1.y * c1.y + r1.z * c1.z + r1.w * c1.w;
            float4 r2 = *(const float4*)(rp + (j + 2) * 4);
            float4 c2 = *(const float4*)(cp + (j + 2) * 4);
            a2 += r2.x * c2.x + r2.y * c2.y + r2.z * c2.z + r2.w * c2.w;
            float4 r3 = *(const float4*)(rp + (j + 3) * 4);
            float4 c3 = *(const float4*)(cp + (j + 3) * 4);
            a3 += r3.x * c3.x + r3.y * c3.y + r3.z * c3.z + r3.w * c3.w;
        }
        float d = (a0 + a1) + (a2 + a3);
        s += fminf(0.f, d * INV_T - lse);
    }
    s += __shfl_xor_sync(0xffffffffu, s, 16);
    s += __shfl_xor_sync(0xffffffffu, s, 8);
    s += __shfl_xor_sync(0xffffffffu, s, 4);
    s += __shfl_xor_sync(0xffffffffu, s, 2);
    s += __shfl_xor_sync(0xffffffffu, s, 1);
    int cnt = (end - off) - (exc ? 1 : 0);
    if (lane == 0) g_rowVal[w] = s / (float)cnt;

    // ---- fused final reduction (last block) ----
    __threadfence();
    __syncthreads();
    if (tid == 0) {
        unsigned t = atomicAdd(&g_ctr, 1u);
        amLast = (t == gridDim.x - 1);
    }
    __syncthreads();
    if (amLast) {
        float a = 0.f;
        for (int i = tid; i < NR; i += 256) a += g_rowVal[i];
        sr[tid] = a;
        __syncthreads();
        for (int st = 128; st; st >>= 1) {
            if (tid < st) sr[tid] += sr[tid + st];
            __syncthreads();
        }
        if (tid == 0) {
            float loss = -(sr[0] / (float)NR);
            out[0] = loss; out[1] = loss; out[2] = loss;
        }
    }
}

// ---------------------------------------------------------------------------
extern "C" void kernel_launch(void* const* d_in, const int* in_sizes, int n_in,
                              void* d_out, int out_size)
{
    const float* feat  = (const float*)d_in[0];
    const int*   label = (const int*)d_in[1];
    const float* fq    = (const float*)d_in[2];
    const float* fq2   = (const float*)d_in[3];
    const int*   lq    = (const int*)d_in[4];
    float* out = (float*)d_out;

    kprep<<<(N2 * 32) / 256, 256>>>(feat, label, fq, fq2, lq);
    kbucket<<<1, 1024>>>();
    kgemm<<<NR / 32, 256>>>();
    krow<<<NR / 8, 256>>>(out);
}

// round 3
// speedup vs baseline: 2.6823x; 1.6598x over previous
#include <cuda_runtime.h>
#include <cuda_bf16.h>
#include <cstdint>

// ---------------------------------------------------------------------------
// SupConLossWithQueue:  Q=4096, bsz=256, B=4352, 2B=8704, D=128, T=0.07
// selected rows g in [3841, 8193)
//   log_prob(g,c) = d(g,c)/T - log( sum_{lab(c')!=lab(g)} exp(d(g,c')/T) )
//   (row-max cancels; d/T <= 14.3 so fp32 sum-exp needs no max tracking)
// GEMM epilogue stores positive logits x=d/T densely by class-rank, so the
// second pass never touches feature vectors.
// ---------------------------------------------------------------------------
#define Qn      4096
#define BSZh    256
#define Bn      4352
#define N2      8704
#define Dk      128
#define ROW0    3841
#define NR      4352
#define NCLS    100
#define MAXP    512
#define NQ      4            // N-range quarters
#define NCOLQ   2176         // cols per quarter
#define INV_T   14.2857142857142857f

__device__ __nv_bfloat16 g_cB[N2][Dk];
__device__ int           g_lab[N2];
__device__ int           g_pk[N2];          // (rank<<16) | label
__device__ int           g_clsOff[NCLS + 1];
__device__ float         g_rowZ[NR][NQ];
__device__ float         g_posD[NR * MAXP];
__device__ float         g_rowVal[NR];
__device__ unsigned int  g_ctr;

// ---------------------------------------------------------------------------
// Kernel P: gather contrast rows (bf16) + labels
// ---------------------------------------------------------------------------
__global__ void __launch_bounds__(256) kprep(const float* __restrict__ feat,
                                             const int*   __restrict__ label,
                                             const float* __restrict__ fq,
                                             const float* __restrict__ fq2,
                                             const int*   __restrict__ lq)
{
    int gid = blockIdx.x * 256 + threadIdx.x;
    int c = gid >> 5, q = gid & 31;
    int half = (c >= Bn) ? 1 : 0;
    int i = c - half * Bn;

    const float* src;
    if (i < BSZh)      src = feat + (half ? i : (BSZh + i)) * Dk;
    else if (i < Qn)   src = (half ? fq2 : fq) + i * Dk;
    else               src = feat + ((half ? BSZh : 0) + (i - Qn)) * Dk;

    float4 v = *(const float4*)(src + q * 4);
    __nv_bfloat162 b01, b23;
    b01.x = __float2bfloat16(v.x); b01.y = __float2bfloat16(v.y);
    b23.x = __float2bfloat16(v.z); b23.y = __float2bfloat16(v.w);
    *(__nv_bfloat162*)(&g_cB[c][q * 4])     = b01;
    *(__nv_bfloat162*)(&g_cB[c][q * 4 + 2]) = b23;
    if (q == 0) {
        int L = (i < BSZh) ? label[i] : ((i < Qn) ? lq[i] : label[i - Qn]);
        g_lab[c] = L;
    }
}

// ---------------------------------------------------------------------------
// Kernel B: class histogram + prefix + per-column rank (packed with label)
// ---------------------------------------------------------------------------
__global__ void kbucket()
{
    __shared__ int scnt[NCLS], soff[NCLS + 1];
    int tid = threadIdx.x;   // 1024
    if (tid < NCLS) scnt[tid] = 0;
    __syncthreads();
    for (int c = tid; c < N2; c += 1024) atomicAdd(&scnt[g_lab[c]], 1);
    __syncthreads();
    if (tid == 0) {
        int run = 0;
        for (int k = 0; k < NCLS; k++) { soff[k] = run; run += scnt[k]; }
        soff[NCLS] = run;
        g_ctr = 0u;
    }
    __syncthreads();
    if (tid <= NCLS) g_clsOff[tid] = soff[tid];
    if (tid < NCLS)  scnt[tid] = 0;
    __syncthreads();
    for (int c = tid; c < N2; c += 1024) {
        int l = g_lab[c];
        int rank = atomicAdd(&scnt[l], 1);
        g_pk[c] = l | (rank << 16);
    }
}

// ---------------------------------------------------------------------------
// Kernel G: bf16 MMA GEMM (M-tile 128, N-quarter 2176) fused with masked
// sum-of-exp + dense positive-logit scatter. grid (34, 4) x 256 threads.
// ---------------------------------------------------------------------------
#define SMT_BYTES (128 * 272 + 512)

__device__ __forceinline__ void mma16816(float* c, const uint32_t* a, uint32_t b0, uint32_t b1)
{
    asm volatile(
        "mma.sync.aligned.m16n8k16.row.col.f32.bf16.bf16.f32 "
        "{%0,%1,%2,%3}, {%4,%5,%6,%7}, {%8,%9}, {%0,%1,%2,%3};\n"
        : "+f"(c[0]), "+f"(c[1]), "+f"(c[2]), "+f"(c[3])
        : "r"(a[0]), "r"(a[1]), "r"(a[2]), "r"(a[3]), "r"(b0), "r"(b1));
}

__global__ void __launch_bounds__(256) kgemm()
{
    __shared__ __align__(16) unsigned char sm[SMT_BYTES];
    __nv_bfloat16* sT = (__nv_bfloat16*)sm;        // A staging, then B tiles
    int* sPk = (int*)(sm + 128 * 272);

    const int tid  = threadIdx.x;
    const int lane = tid & 31;
    const int wid  = tid >> 5;          // warp owns rows wid*16 .. +15
    const int rowbase = blockIdx.x * 128;
    const int colbase = blockIdx.y * NCOLQ;

    // --- B prefetch regs (first tile of this quarter) ---
    const int br0 = tid >> 4, bch = tid & 15;
    uint4 breg[8];
#pragma unroll
    for (int j = 0; j < 8; j++)
        breg[j] = *(const uint4*)((const char*)g_cB[colbase + br0 + j * 16] + bch * 16);
    int pkreg = (tid < 128) ? g_pk[colbase + tid] : 0;

    // --- stage A (128 rows x 256B) into smem, then preload frags ---
    for (int idx = tid; idx < 128 * 16; idx += 256) {
        int r = idx >> 4, ch = idx & 15;
        *(uint4*)((char*)sT + r * 272 + ch * 16) =
            *(const uint4*)((const char*)g_cB[ROW0 + rowbase + r] + ch * 16);
    }
    __syncthreads();

    uint32_t afr[8][4];
    {
        uint32_t abase = (uint32_t)__cvta_generic_to_shared(sT);
        uint32_t addr0 = abase + (wid * 16 + (lane & 15)) * 272 + ((lane >> 4) << 4);
#pragma unroll
        for (int ks = 0; ks < 8; ks++) {
            asm volatile("ldmatrix.sync.aligned.m8n8.x4.shared.b16 {%0,%1,%2,%3}, [%4];"
                         : "=r"(afr[ks][0]), "=r"(afr[ks][1]), "=r"(afr[ks][2]), "=r"(afr[ks][3])
                         : "r"(addr0 + ks * 32));
        }
    }
    __syncthreads();   // all A frags read; sT now reusable for B

    const int w0 = rowbase + wid * 16 + (lane >> 2);
    const int w1 = w0 + 8;
    const int rl0 = g_lab[ROW0 + w0];
    const int rl1 = g_lab[ROW0 + w1];
    float z0 = 0.f, z1 = 0.f;

    uint32_t bbase = (uint32_t)__cvta_generic_to_shared(sT);
    const int bj = lane >> 3;
    const int bn_off = ((bj & 2) << 2) + (lane & 7);
    const uint32_t bk_off = (uint32_t)((bj & 1) << 4);

    for (int nb = 0; nb < NCOLQ / 128; nb++) {
        // commit prefetched tile
#pragma unroll
        for (int j = 0; j < 8; j++)
            *(uint4*)((char*)sT + (br0 + j * 16) * 272 + bch * 16) = breg[j];
        if (tid < 128) sPk[tid] = pkreg;
        __syncthreads();

        if (nb + 1 < NCOLQ / 128) {
            int n0n = colbase + (nb + 1) * 128;
#pragma unroll
            for (int j = 0; j < 8; j++)
                breg[j] = *(const uint4*)((const char*)g_cB[n0n + br0 + j * 16] + bch * 16);
            if (tid < 128) pkreg = g_pk[n0n + tid];
        }

        // MMA: 16(M) x 128(N) per warp, K=128
        float acc[16][4] = {};
#pragma unroll
        for (int ks = 0; ks < 8; ks++) {
#pragma unroll
            for (int gix = 0; gix < 8; gix++) {
                uint32_t ba = bbase + (uint32_t)((gix * 16 + bn_off) * 272)
                              + (uint32_t)(ks * 32) + bk_off;
                uint32_t b0, b1, b2, b3;
                asm volatile("ldmatrix.sync.aligned.m8n8.x4.shared.b16 {%0,%1,%2,%3}, [%4];"
                             : "=r"(b0), "=r"(b1), "=r"(b2), "=r"(b3) : "r"(ba));
                mma16816(acc[2 * gix],     afr[ks], b0, b1);
                mma16816(acc[2 * gix + 1], afr[ks], b2, b3);
            }
        }

        // epilogue: masked sum-of-exp + positive scatter
#pragma unroll
        for (int f = 0; f < 16; f++) {
            int2 pk = *(const int2*)&sPk[f * 8 + 2 * (lane & 3)];
            int l0 = pk.x & 0xffff, l1 = pk.y & 0xffff;
            float x00 = acc[f][0] * INV_T, x01 = acc[f][1] * INV_T;
            float x10 = acc[f][2] * INV_T, x11 = acc[f][3] * INV_T;
            bool e00 = (l0 == rl0), e01 = (l1 == rl0);
            bool e10 = (l0 == rl1), e11 = (l1 == rl1);
            z0 += __expf(e00 ? -2e30f : x00) + __expf(e01 ? -2e30f : x01);
            z1 += __expf(e10 ? -2e30f : x10) + __expf(e11 ? -2e30f : x11);
            if (e00) g_posD[w0 * MAXP + (pk.x >> 16)] = x00;
            if (e01) g_posD[w0 * MAXP + (pk.y >> 16)] = x01;
            if (e10) g_posD[w1 * MAXP + (pk.x >> 16)] = x10;
            if (e11) g_posD[w1 * MAXP + (pk.y >> 16)] = x11;
        }
        __syncthreads();   // done with sPk/sT before next commit
    }

    // reduce z across the 4 lanes sharing each row
    z0 += __shfl_xor_sync(0xffffffffu, z0, 1);
    z0 += __shfl_xor_sync(0xffffffffu, z0, 2);
    z1 += __shfl_xor_sync(0xffffffffu, z1, 1);
    z1 += __shfl_xor_sync(0xffffffffu, z1, 2);
    if ((lane & 3) == 0) {
        g_rowZ[w0][blockIdx.y] = z0;
        g_rowZ[w1][blockIdx.y] = z1;
    }
}

// ---------------------------------------------------------------------------
// Kernel R: warp per row over dense positive list + fused final mean
// ---------------------------------------------------------------------------
__global__ void __launch_bounds__(256) krow(float* __restrict__ out)
{
    __shared__ float sr[256];
    __shared__ bool amLast;

    int tid = threadIdx.x, lane = tid & 31, wid = tid >> 5;
    int w = blockIdx.x * 8 + wid;
    int g = ROW0 + w;
    int rl = g_lab[g];
    bool exc = (g < Bn) || (g == 8192);
    int off = g_clsOff[rl];
    int cnt = g_clsOff[rl + 1] - off;
    int selfRank = g_pk[g] >> 16;

    float4 zz = *(const float4*)g_rowZ[w];
    float lse = __logf((zz.x + zz.y) + (zz.z + zz.w));

    float s = 0.f;
    for (int idx = lane; idx < cnt; idx += 32) {
        if (exc && idx == selfRank) continue;
        float x = g_posD[w * MAXP + idx];
        s += fminf(0.f, x - lse);
    }
    s += __shfl_xor_sync(0xffffffffu, s, 16);
    s += __shfl_xor_sync(0xffffffffu, s, 8);
    s += __shfl_xor_sync(0xffffffffu, s, 4);
    s += __shfl_xor_sync(0xffffffffu, s, 2);
    s += __shfl_xor_sync(0xffffffffu, s, 1);
    if (lane == 0) g_rowVal[w] = s / (float)(cnt - (exc ? 1 : 0));

    // fused final mean (last block)
    __threadfence();
    __syncthreads();
    if (tid == 0) {
        unsigned t = atomicAdd(&g_ctr, 1u);
        amLast = (t == gridDim.x - 1);
    }
    __syncthreads();
    if (amLast) {
        float a = 0.f;
        for (int i = tid; i < NR; i += 256) a += g_rowVal[i];
        sr[tid] = a;
        __syncthreads();
        for (int st = 128; st; st >>= 1) {
            if (tid < st) sr[tid] += sr[tid + st];
            __syncthreads();
        }
        if (tid == 0) {
            float loss = -(sr[0] / (float)NR);
            out[0] = loss; out[1] = loss; out[2] = loss;
        }
    }
}

// ---------------------------------------------------------------------------
extern "C" void kernel_launch(void* const* d_in, const int* in_sizes, int n_in,
                              void* d_out, int out_size)
{
    const float* feat  = (const float*)d_in[0];
    const int*   label = (const int*)d_in[1];
    const float* fq    = (const float*)d_in[2];
    const float* fq2   = (const float*)d_in[3];
    const int*   lq    = (const int*)d_in[4];
    float* out = (float*)d_out;

    kprep<<<(N2 * 32) / 256, 256>>>(feat, label, fq, fq2, lq);
    kbucket<<<1, 1024>>>();
    kgemm<<<dim3(NR / 128, NQ), 256>>>();
    krow<<<NR / 8, 256>>>(out);
}